// round 17
// baseline (speedup 1.0000x reference)
#include <cuda_runtime.h>
#include <cuda_fp16.h>
#include <cstdint>
#include <cfloat>

#define K_CODES 1024
#define DIM     256
#define T_LEN   4096
#define B_SZ    16
#define N_ROWS  65536
#define QN      ((size_t)16777216)
#define RS      528                     // smem row stride (512B data + 16B pad)
#define TM      32                      // rows per CTA
#define NCODE   64                      // codes per B chunk
#define NCH     (K_CODES / NCODE)       // 16 chunks
#define A_BYTES (TM * RS)               // 16896
#define B_BYTES (NCODE * RS)            // 33792
#define XTRA    (A_BYTES + 2 * B_BYTES) // 84480
#define SMEM_M  (XTRA + 2048)           // 86528 -> 2 CTAs/SM
#define NTHR    256
#define RTHR    256
#define RGRID   128

__device__ __align__(256) __half g_Bh[(size_t)K_CODES * DIM];   // fp16 normalized emb
__device__ __align__(256) float g_enT[DIM * K_CODES];           // fp32 normalized emb^T
__device__ float g_elen[K_CODES];
__device__ float g_e2[K_CODES];
__device__ int   g_rn;
__device__ int   g_rlist[N_ROWS];

__device__ __forceinline__ void cp16(uint32_t dst, const void* src) {
    asm volatile("cp.async.cg.shared.global [%0], [%1], 16;\n" :: "r"(dst), "l"(src));
}
__device__ __forceinline__ void cp_commit() { asm volatile("cp.async.commit_group;\n"); }
template <int N> __device__ __forceinline__ void cp_waitg() {
    asm volatile("cp.async.wait_group %0;\n" :: "n"(N));
}
__device__ __forceinline__ void ldsm4(uint32_t* r, uint32_t a) {
    asm volatile("ldmatrix.sync.aligned.m8n8.x4.shared.b16 {%0,%1,%2,%3}, [%4];"
                 : "=r"(r[0]), "=r"(r[1]), "=r"(r[2]), "=r"(r[3]) : "r"(a));
}
__device__ __forceinline__ void ldsm2(uint32_t* r, uint32_t a) {
    asm volatile("ldmatrix.sync.aligned.m8n8.x2.shared.b16 {%0,%1}, [%2];"
                 : "=r"(r[0]), "=r"(r[1]) : "r"(a));
}
__device__ __forceinline__ void mma16816(float* c, const uint32_t* a, const uint32_t* b) {
    asm volatile(
        "mma.sync.aligned.m16n8k16.row.col.f32.f16.f16.f32 "
        "{%0,%1,%2,%3},{%4,%5,%6,%7},{%8,%9},{%0,%1,%2,%3};"
        : "+f"(c[0]), "+f"(c[1]), "+f"(c[2]), "+f"(c[3])
        : "r"(a[0]), "r"(a[1]), "r"(a[2]), "r"(a[3]), "r"(b[0]), "r"(b[1]));
}

// --------- prep B: normalize emb -> g_enT + g_Bh, norms, zero counters -----
__global__ void vq_prepB(const float* __restrict__ emb,
                         float* __restrict__ out, long long out_size) {
    int k = blockIdx.x, d = threadIdx.x;
    float v = emb[(size_t)k * DIM + d];
    float s = v * v;
    #pragma unroll
    for (int o = 16; o; o >>= 1) s += __shfl_xor_sync(0xFFFFFFFFu, s, o);
    __shared__ float ws[8]; __shared__ float rs_sh;
    if ((d & 31) == 0) ws[d >> 5] = s;
    __syncthreads();
    if (d == 0) {
        float t = 0.f;
        #pragma unroll
        for (int i = 0; i < 8; i++) t += ws[i];
        float nrm = sqrtf(t);
        rs_sh = 1.0f / fmaxf(nrm, 1e-12f);
        g_elen[k] = nrm;
        g_e2[k] = t;
        if (k == 0) {
            g_rn = 0;
            if (out_size > (long long)QN) out[QN] = 0.0f;
        }
    }
    __syncthreads();
    float en = v * rs_sh;
    g_enT[(size_t)d * K_CODES + k] = en;
    g_Bh[(size_t)k * DIM + d] = __float2half_rn(en);
}

// --------- main: TM=32, barrier-free mainloop, fp16 mma.sync + argmax -------
__global__ void __launch_bounds__(NTHR, 2) vq_main_kernel(
    const float* __restrict__ x, const float* __restrict__ emb,
    float* __restrict__ out, long long out_size)
{
    extern __shared__ char smem[];
    const uint32_t sb = (uint32_t)__cvta_generic_to_shared(smem);
    const uint32_t sbB = sb + A_BYTES;
    const int tid  = threadIdx.x;
    const int lane = tid & 31;
    const int wn   = tid >> 5;           // warp owns codes [wn*8, wn*8+8) per chunk
    const int n0 = blockIdx.x * TM;
    const int b  = n0 >> 12;
    const int tl = n0 & 4095;

    float* xpart = (float*)(smem + XTRA);        // [8][32]
    float* xn2   = (float*)(smem + XTRA + 1024); // [32]

    // Warp wn loads its own 8 B rows per chunk (warp-local cp.async groups).
    auto loadB = [&](int nc) {
        const __half* Bsrc = g_Bh + (size_t)(nc * NCODE + wn * 8) * DIM;
        uint32_t stg = sbB + (uint32_t)((nc & 1) * B_BYTES + (wn * 8) * RS);
        #pragma unroll
        for (int i = 0; i < 8; i++)
            cp16(stg + (uint32_t)(i * RS + lane * 16), Bsrc + (size_t)i * DIM + lane * 8);
        cp_commit();
    };
    loadB(0); loadB(1);

    // ---- fused prep A: load x tile, fp16 convert into smem, row norms ----
    {
        const int r = lane;                     // row 0..31
        const int dg = wn;                      // dim group 0..7
        float ss = 0.f;
        #pragma unroll 8
        for (int i = 0; i < 32; i++) {
            int d = i * 8 + dg;
            float v = x[((size_t)b * DIM + d) * T_LEN + tl + r];
            ss = fmaf(v, v, ss);
            *(__half*)(smem + r * RS + d * 2) = __float2half_rn(v);
        }
        xpart[dg * 32 + r] = ss;
    }
    __syncthreads();                             // A tile + xpart visible CTA-wide
    if (tid < TM) {
        float t = 0.f;
        #pragma unroll
        for (int g = 0; g < 8; g++) t += xpart[g * 32 + tid];
        xn2[tid] = t;
    }

    float rm1[4], rm2[4];
    int   ri1[4];
    #pragma unroll
    for (int i = 0; i < 4; i++) { rm1[i] = -FLT_MAX; rm2[i] = -FLT_MAX; ri1[i] = 0; }

    #pragma unroll 1
    for (int nc = 0; nc < NCH; nc++) {
        if (nc < NCH - 2) cp_waitg<1>(); else cp_waitg<0>();
        // no barrier: each warp reads only its own B slice; A is stable.

        float acc[2][4];
        #pragma unroll
        for (int mt = 0; mt < 2; mt++)
            #pragma unroll
            for (int c = 0; c < 4; c++) acc[mt][c] = 0.f;

        const uint32_t stgB = sbB + (uint32_t)(nc & 1) * B_BYTES;
        #pragma unroll 4
        for (int ks = 0; ks < 16; ks++) {
            uint32_t af[2][4], bf[2];
            #pragma unroll
            for (int mt = 0; mt < 2; mt++) {
                int row = mt * 16 + (lane & 15);
                ldsm4(af[mt], sb + (uint32_t)(row * RS + ks * 32 + (lane >> 4) * 16));
            }
            {
                int rb = wn * 8 + (lane & 7);
                ldsm2(bf, stgB + (uint32_t)(rb * RS + ks * 32 + ((lane >> 3) & 1) * 16));
            }
            #pragma unroll
            for (int mt = 0; mt < 2; mt++)
                mma16816(acc[mt], af[mt], bf);
        }

        {
            int cb = nc * NCODE + wn * 8 + 2 * (lane & 3);
            #pragma unroll
            for (int mt = 0; mt < 2; mt++)
                #pragma unroll
                for (int c = 0; c < 4; c++) {
                    int slot = mt * 2 + (c >> 1);
                    int ci = cb + (c & 1);
                    float v = acc[mt][c];
                    if (v > rm1[slot]) { rm2[slot] = rm1[slot]; rm1[slot] = v; ri1[slot] = ci; }
                    else if (v > rm2[slot]) rm2[slot] = v;
                }
        }
        if (nc + 2 < NCH) loadB(nc + 2);         // warp-local; own slice already consumed
    }
    __syncthreads();

    // ---- cross-partition top-2 reduce: [32 rows][32 partitions] ----
    float* redm1 = (float*)smem;                 // 4KB
    int*   redix = (int*)(smem + 4096);
    float* redm2 = (float*)(smem + 8192);
    const int p = wn * 4 + (lane & 3);
    #pragma unroll
    for (int slot = 0; slot < 4; slot++) {
        int row = (slot >> 1) * 16 + (slot & 1) * 8 + (lane >> 2);
        redm1[row * 32 + p] = rm1[slot];
        redix[row * 32 + p] = ri1[slot];
        redm2[row * 32 + p] = rm2[slot];
    }
    __syncthreads();

    int*   idx_s = (int*)(smem + 12288);         // [32]
    float* bestv = (float*)(smem + 12416);       // [32]
    int*   flg   = (int*)(smem + 12544);         // [32]

    if (tid < TM) {
        float g1 = -FLT_MAX, g2 = -FLT_MAX; int gi = 0;
        #pragma unroll 1
        for (int j = 0; j < 32; j++) {
            float m1 = redm1[tid * 32 + j];
            float m2 = redm2[tid * 32 + j];
            int   ix = redix[tid * 32 + j];
            if (m1 > g1) { g2 = fmaxf(fmaxf(g1, m2), g2); g1 = m1; gi = ix; }
            else         { g2 = fmaxf(g2, m1); }
        }
        idx_s[tid] = gi;
        bestv[tid] = g1;
        int f = (g1 - g2 < 2e-4f * sqrtf(xn2[tid])) ? 1 : 0;  // fp16-dot 10+ sigma
        flg[tid] = f;
        if (f) {
            int q = atomicAdd(&g_rn, 1);
            g_rlist[q] = n0 + tid;
        }
    }
    __syncthreads();

    if (tid < TM && !flg[tid] && out_size >= (long long)(QN + 1 + N_ROWS))
        out[QN + 1 + n0 + tid] = (float)idx_s[tid];

    // ---- loss from norms (per-row, non-flagged) ----
    if (tid < TM) {
        float lr = 0.f;
        if (!flg[tid]) {
            int gi = idx_s[tid];
            lr = xn2[tid] - 2.0f * g_elen[gi] * bestv[tid] + g_e2[gi];
        }
        redm1[tid] = lr;
    }
    __syncthreads();
    if (tid == 0 && out_size > (long long)QN) {
        float t = 0.f;
        #pragma unroll 1
        for (int j = 0; j < TM; j++) t += redm1[j];
        atomicAdd(out + QN, t * (1.25f / 16777216.0f));
    }

    // ---- gather + quantized write (non-flagged rows) ----
    const int r  = lane;
    const int dq = wn;                           // 8 segments of 32 dims
    if (!flg[r]) {
        const int myidx = idx_s[r];
        const float4* erow4 = (const float4*)(emb + (size_t)myidx * DIM + dq * 32);
        float* ob = out + ((size_t)b * DIM + dq * 32) * T_LEN + tl + r;
        #pragma unroll 8
        for (int dj = 0; dj < 8; ++dj) {
            float4 e4 = erow4[dj];
            int d = dj * 4;
            ob[(size_t)(d + 0) * T_LEN] = e4.x;
            ob[(size_t)(d + 1) * T_LEN] = e4.y;
            ob[(size_t)(d + 2) * T_LEN] = e4.z;
            ob[(size_t)(d + 3) * T_LEN] = e4.w;
        }
    }
}

// --------- rescue: exact fp32 argmax + outputs for flagged rows -------------
__global__ void __launch_bounds__(RTHR, 2) vq_rescue(
    const float* __restrict__ x, const float* __restrict__ emb,
    float* __restrict__ out, long long out_size)
{
    __shared__ float xs8[8 * 256];
    __shared__ float xn8[8];
    __shared__ float rwv[8 * 8];
    __shared__ int   rwi[8 * 8];
    __shared__ int   bsel[8];
    const int tid = threadIdx.x, lane = tid & 31, wid = tid >> 5;
    const int total = g_rn;

    #pragma unroll 1
    for (int base = blockIdx.x * 8; base < total; base += gridDim.x * 8) {
        const int nb = min(8, total - base);
        #pragma unroll
        for (int i = 0; i < 8; i++) {
            int lin = i * RTHR + tid;
            int r = lin >> 8, d = lin & 255;
            int nn = g_rlist[base + (r < nb ? r : 0)];
            xs8[r * 256 + d] = x[((size_t)(nn >> 12) * DIM + d) * T_LEN + (nn & 4095)];
        }
        __syncthreads();
        {
            float s = 0.f;
            #pragma unroll
            for (int j = 0; j < 8; j++) {
                float v = xs8[wid * 256 + lane + 32 * j];
                s = fmaf(v, v, s);
            }
            #pragma unroll
            for (int o = 16; o; o >>= 1) s += __shfl_xor_sync(0xFFFFFFFFu, s, o);
            if (lane == 0) xn8[wid] = s;
        }
        float a0[8], a1[8], a2[8], a3[8];
        #pragma unroll
        for (int r = 0; r < 8; r++) { a0[r] = 0.f; a1[r] = 0.f; a2[r] = 0.f; a3[r] = 0.f; }
        #pragma unroll 4
        for (int d = 0; d < 256; d++) {
            const float* ed = g_enT + d * K_CODES + tid;
            float e0 = ed[0], e1 = ed[256], e2v = ed[512], e3 = ed[768];
            #pragma unroll
            for (int r = 0; r < 8; r++) {
                float xv = xs8[r * 256 + d];
                a0[r] = fmaf(xv, e0, a0[r]);
                a1[r] = fmaf(xv, e1, a1[r]);
                a2[r] = fmaf(xv, e2v, a2[r]);
                a3[r] = fmaf(xv, e3, a3[r]);
            }
        }
        #pragma unroll 1
        for (int r = 0; r < nb; r++) {
            float bv = a0[r]; int bi = tid;
            if (a1[r] > bv) { bv = a1[r]; bi = tid + 256; }
            if (a2[r] > bv) { bv = a2[r]; bi = tid + 512; }
            if (a3[r] > bv) { bv = a3[r]; bi = tid + 768; }
            #pragma unroll
            for (int o = 16; o; o >>= 1) {
                float ov = __shfl_xor_sync(0xFFFFFFFFu, bv, o);
                int   oi = __shfl_xor_sync(0xFFFFFFFFu, bi, o);
                if (ov > bv || (ov == bv && oi < bi)) { bv = ov; bi = oi; }
            }
            if (lane == 0) { rwv[r * 8 + wid] = bv; rwi[r * 8 + wid] = bi; }
        }
        __syncthreads();
        if (tid < nb) {
            float best = rwv[tid * 8]; int besti = rwi[tid * 8];
            #pragma unroll
            for (int j = 1; j < 8; j++) {
                float v = rwv[tid * 8 + j]; int ix = rwi[tid * 8 + j];
                if (v > best || (v == best && ix < besti)) { best = v; besti = ix; }
            }
            bsel[tid] = besti;
            int nn = g_rlist[base + tid];
            if (out_size >= (long long)(QN + 1 + N_ROWS))
                out[QN + 1 + nn] = (float)besti;
            if (out_size > (long long)QN)
                atomicAdd(out + QN,
                    (xn8[tid] - 2.0f * g_elen[besti] * best + g_e2[besti]) * (1.25f / 16777216.0f));
        }
        __syncthreads();
        #pragma unroll 1
        for (int r = 0; r < nb; r++) {
            int nn = g_rlist[base + r];
            int bi = bsel[r];
            out[((size_t)(nn >> 12) * DIM + tid) * T_LEN + (nn & 4095)] =
                emb[(size_t)bi * DIM + tid];
        }
        __syncthreads();
    }
}

// ---------------------------------------------------------------------------
extern "C" void kernel_launch(void* const* d_in, const int* in_sizes, int n_in,
                              void* d_out, int out_size) {
    const float* x   = (const float*)d_in[0];
    const float* emb = (const float*)d_in[1];
    if (n_in >= 2 && in_sizes[0] == K_CODES * DIM && in_sizes[1] == (int)QN) {
        const float* t = x; x = emb; emb = t;
    }
    float* out = (float*)d_out;

    cudaFuncSetAttribute(vq_main_kernel, cudaFuncAttributeMaxDynamicSharedMemorySize, SMEM_M);

    vq_prepB<<<K_CODES, 256>>>(emb, out, (long long)out_size);
    vq_main_kernel<<<N_ROWS / TM, NTHR, SMEM_M>>>(x, emb, out, (long long)out_size);
    vq_rescue<<<RGRID, RTHR>>>(x, emb, out, (long long)out_size);
}